// round 15
// baseline (speedup 1.0000x reference)
#include <cuda_runtime.h>
#include <math.h>

#define NP     100
#define BATCH  256
#define FD     256
#define NOUT   30

// precomputed (cos, sin) of half-angles, packed as float4 pairs for aligned stores
__device__ float4       g_scs4[BATCH][(3 * NP) / 2];
__device__ float        g_m[3][BATCH][NOUT];
__device__ unsigned int g_cnt[BATCH];

// ---------------- kernel 1: param GEMM + sincos, 4 params per block ----------------
// grid 150: blockIdx = quad(75) * 2 + batch-half(2); 256 threads = 8 warps x 16 batches
__global__ void __launch_bounds__(256) qsb_params(
    const float* __restrict__ x,
    const float* __restrict__ W1, const float* __restrict__ b1, const float* __restrict__ base1,
    const float* __restrict__ W2, const float* __restrict__ b2, const float* __restrict__ base2,
    const float* __restrict__ W3, const float* __restrict__ b3, const float* __restrict__ base3)
{
    const int qq  = blockIdx.x >> 1;          // param quad 0..74
    const int h   = blockIdx.x & 1;           // batch half
    const int jj0 = qq * 4;                   // global param idx (quads never straddle branches)
    const int br  = jj0 / NP;
    const int j0  = jj0 - br * NP;
    const float* __restrict__ W  = (br == 0) ? W1 : (br == 1) ? W2 : W3;
    const float* __restrict__ bb = (br == 0) ? b1 : (br == 1) ? b2 : b3;
    const float* __restrict__ bs = (br == 0) ? base1 : (br == 1) ? base2 : base3;

    const int lane = threadIdx.x & 31;
    const int wid  = threadIdx.x >> 5;        // 0..7

    float4 wa[4], wb[4];
    float bias[4];
    #pragma unroll
    for (int r = 0; r < 4; ++r) {
        const float4* __restrict__ w4 = (const float4*)(W + (j0 + r) * FD);
        wa[r] = w4[lane];
        wb[r] = w4[lane + 32];
        bias[r] = bb[j0 + r] + bs[j0 + r];
    }

    #pragma unroll 2
    for (int t = 0; t < 16; ++t) {
        const int bt = h * 128 + wid * 16 + t;
        const float4* __restrict__ x4 = (const float4*)(x + bt * FD);
        float4 xa = x4[lane];
        float4 xb = x4[lane + 32];
        float s[4];
        #pragma unroll
        for (int r = 0; r < 4; ++r) {
            s[r] = wa[r].x*xa.x + wa[r].y*xa.y + wa[r].z*xa.z + wa[r].w*xa.w
                 + wb[r].x*xb.x + wb[r].y*xb.y + wb[r].z*xb.z + wb[r].w*xb.w;
        }
        #pragma unroll
        for (int o = 16; o; o >>= 1) {
            s[0] += __shfl_xor_sync(0xffffffffu, s[0], o);
            s[1] += __shfl_xor_sync(0xffffffffu, s[1], o);
            s[2] += __shfl_xor_sync(0xffffffffu, s[2], o);
            s[3] += __shfl_xor_sync(0xffffffffu, s[3], o);
        }
        if (lane == 0) {
            float c[4], n[4];
            #pragma unroll
            for (int r = 0; r < 4; ++r) {
                float hh = 3.14159265358979f / (1.0f + __expf(-(s[r] + bias[r])));
                __sincosf(hh, &n[r], &c[r]);
            }
            g_scs4[bt][jj0 / 2]     = make_float4(c[0], n[0], c[1], n[1]);
            g_scs4[bt][jj0 / 2 + 1] = make_float4(c[2], n[2], c[3], n[3]);
        }
    }
}

// ---------------- circuit machinery ----------------
// Storage map (wire -> storage bit): regs bits 0..2, lanes 3..7, warps 8..9
//  wire: 0   1   2   3   4   5   6   7   8   9
//  bit : 7   2   6   1   5   0   4   8   3   9

template<int B>
__device__ __forceinline__ void apply1q(float* vr, float* vi, int lane,
    float U00r, float U00i, float U01r, float U01i,
    float U10r, float U10i, float U11r, float U11i)
{
    if constexpr (B < 3) {
        constexpr int st = 1 << B;
        #pragma unroll
        for (int q = 0; q < 4; ++q) {
            const int m0 = ((q >> B) << (B + 1)) | (q & (st - 1));
            const int m1 = m0 | st;
            float a0r = vr[m0], a0i = vi[m0], a1r = vr[m1], a1i = vi[m1];
            vr[m0] = U00r*a0r - U00i*a0i + U01r*a1r - U01i*a1i;
            vi[m0] = U00r*a0i + U00i*a0r + U01r*a1i + U01i*a1r;
            vr[m1] = U10r*a0r - U10i*a0i + U11r*a1r - U11i*a1i;
            vi[m1] = U10r*a0i + U10i*a0r + U11r*a1i + U11i*a1r;
        }
    } else {
        constexpr int lm = 1 << (B - 3);
        const bool r = (lane & lm) != 0;
        float cmr = r ? U11r : U00r, cmi = r ? U11i : U00i;
        float cpr = r ? U10r : U01r, cpi = r ? U10i : U01i;
        #pragma unroll
        for (int m = 0; m < 8; ++m) {
            float pr = __shfl_xor_sync(0xffffffffu, vr[m], lm);
            float pi = __shfl_xor_sync(0xffffffffu, vi[m], lm);
            float mr = vr[m], mi = vi[m];
            vr[m] = cmr*mr - cmi*mi + cpr*pr - cpi*pi;
            vi[m] = cmr*mi + cmi*mr + cpr*pi + cpi*pr;
        }
    }
}

template<int WM>
__device__ __forceinline__ void apply1qW(float* vr, float* vi, int t7, int w,
    float2 (*ex)[128],
    float U00r, float U00i, float U01r, float U01i,
    float U10r, float U10i, float U11r, float U11i)
{
    const bool hi = (w & WM) != 0;
    float cmr = hi ? U11r : U00r, cmi = hi ? U11i : U00i;
    float cpr = hi ? U10r : U01r, cpi = hi ? U10i : U01i;
    __syncthreads();
    #pragma unroll
    for (int m = 0; m < 8; ++m) ex[m][t7] = make_float2(vr[m], vi[m]);
    __syncthreads();
    const int p = t7 ^ (WM << 5);
    #pragma unroll
    for (int m = 0; m < 8; ++m) {
        float2 pv = ex[m][p];
        float mr = vr[m], mi = vi[m];
        vr[m] = cmr*mr - cmi*mi + cpr*pv.x - cpi*pv.y;
        vi[m] = cmr*mi + cmi*mr + cpr*pv.y + cpi*pv.x;
    }
}

template<int BC, int BT>
__device__ __forceinline__ void applycrx(float* vr, float* vi, int lane, int w, float cg, float sg)
{
    bool act = true;
    if constexpr (BC >= 8)      act = (w & (1 << (BC - 8))) != 0;
    else if constexpr (BC >= 3) act = (lane & (1 << (BC - 3))) != 0;

    if constexpr (BT < 3) {
        constexpr int tm = 1 << BT;
        if constexpr (BC < 3) {
            #pragma unroll
            for (int m0 = 0; m0 < 8; ++m0)
                if ((m0 & (1 << BC)) && !(m0 & tm)) {
                    const int m1 = m0 | tm;
                    float a0r = vr[m0], a0i = vi[m0], a1r = vr[m1], a1i = vi[m1];
                    vr[m0] = cg*a0r + sg*a1i; vi[m0] = cg*a0i - sg*a1r;
                    vr[m1] = cg*a1r + sg*a0i; vi[m1] = cg*a1i - sg*a0r;
                }
        } else {
            if (act) {
                #pragma unroll
                for (int q = 0; q < 4; ++q) {
                    const int m0 = ((q >> BT) << (BT + 1)) | (q & (tm - 1));
                    const int m1 = m0 | tm;
                    float a0r = vr[m0], a0i = vi[m0], a1r = vr[m1], a1i = vi[m1];
                    vr[m0] = cg*a0r + sg*a1i; vi[m0] = cg*a0i - sg*a1r;
                    vr[m1] = cg*a1r + sg*a0i; vi[m1] = cg*a1i - sg*a0r;
                }
            }
        }
    } else {
        constexpr int lm = 1 << (BT - 3);
        if constexpr (BC < 3) {
            #pragma unroll
            for (int m = 0; m < 8; ++m)
                if (m & (1 << BC)) {
                    float pr = __shfl_xor_sync(0xffffffffu, vr[m], lm);
                    float pi = __shfl_xor_sync(0xffffffffu, vi[m], lm);
                    float mr = vr[m], mi = vi[m];
                    vr[m] = cg*mr + sg*pi; vi[m] = cg*mi - sg*pr;
                }
        } else if constexpr (BC >= 8) {
            if (act) {
                #pragma unroll
                for (int m = 0; m < 8; ++m) {
                    float pr = __shfl_xor_sync(0xffffffffu, vr[m], lm);
                    float pi = __shfl_xor_sync(0xffffffffu, vi[m], lm);
                    float mr = vr[m], mi = vi[m];
                    vr[m] = cg*mr + sg*pi; vi[m] = cg*mi - sg*pr;
                }
            }
        } else {
            #pragma unroll
            for (int m = 0; m < 8; ++m) {
                float pr = __shfl_xor_sync(0xffffffffu, vr[m], lm);
                float pi = __shfl_xor_sync(0xffffffffu, vi[m], lm);
                float mr = vr[m], mi = vi[m];
                float nr = cg*mr + sg*pi, ni = cg*mi - sg*pr;
                vr[m] = act ? nr : mr; vi[m] = act ? ni : mi;
            }
        }
    }
}

template<int WM>
__device__ __forceinline__ void applycrxW(float* vr, float* vi, int t7,
    float2 (*ex)[128], float cg, float sg, bool act)
{
    __syncthreads();
    if (act) {
        #pragma unroll
        for (int m = 0; m < 8; ++m) ex[m][t7] = make_float2(vr[m], vi[m]);
    }
    __syncthreads();
    if (act) {
        const int p = t7 ^ (WM << 5);
        #pragma unroll
        for (int m = 0; m < 8; ++m) {
            float2 pv = ex[m][p];
            float mr = vr[m], mi = vi[m];
            vr[m] = cg*mr + sg*pv.y; vi[m] = cg*mi - sg*pv.x;
        }
    }
}

// ---------------- kernel 2: one circuit per block (grid 768, 128 threads) ----------------
__global__ void __launch_bounds__(128) qsb_circuit(
    const float* __restrict__ ar_, const float* __restrict__ ai_,
    const float* __restrict__ br_, const float* __restrict__ bi_,
    const float* __restrict__ gr_, const float* __restrict__ gi_,
    float* __restrict__ out)
{
    const int bt   = blockIdx.x & 255;
    const int br   = blockIdx.x >> 8;
    const int t7   = threadIdx.x;
    const int lane = t7 & 31;
    const int w    = t7 >> 5;

    __shared__ float2 scs[NP];
    __shared__ float2 ex[8][128];
    __shared__ float  ptbuf[128 * 33];      // per-thread partials, stride 33 (conflict-free)
    __shared__ float  wpart[4][NOUT];
    __shared__ int    sIsLast;

    {   // stage (cos,sin): 100 float2 = 50 float4
        const float2* __restrict__ srow = (const float2*)g_scs4[bt];
        if (t7 < NP) scs[t7] = srow[br * NP + t7];
    }
    __syncthreads();

    float vr[8], vi[8];
    #pragma unroll
    for (int m = 0; m < 8; ++m) { vr[m] = 0.f; vi[m] = 0.f; }
    if (t7 == 0) vr[0] = 1.0f;

    int idx = 0;

    #define UCOEF \
        float2 p1 = scs[idx], p2 = scs[idx+1], p3 = scs[idx+2]; idx += 3; \
        float c1 = p1.x, s1 = p1.y, c2 = p2.x, s2 = p2.y, c3 = p3.x, s3 = p3.y; \
        float A00r =  c2*c1, A00i =  s2*s1; \
        float A01r = -s2*c1, A01i = -c2*s1; \
        float A10r =  s2*c1, A10i = -c2*s1; \
        float A11r =  c2*c1, A11i = -s2*s1; \
        float U00r = c3*A00r + s3*A00i, U00i = c3*A00i - s3*A00r; \
        float U01r = c3*A01r + s3*A01i, U01i = c3*A01i - s3*A01r; \
        float U10r = c3*A10r - s3*A10i, U10i = c3*A10i + s3*A10r; \
        float U11r = c3*A11r - s3*A11i, U11i = c3*A11i + s3*A11r;

    #define FUSED(B) { UCOEF \
        apply1q<B>(vr, vi, lane, U00r,U00i,U01r,U01i,U10r,U10i,U11r,U11i); }
    #define FUSEDW(WM) { UCOEF \
        apply1qW<WM>(vr, vi, t7, w, ex, U00r,U00i,U01r,U01i,U10r,U10i,U11r,U11i); }
    #define CRX(BC,BT) { float2 p = scs[idx]; idx++; \
        applycrx<BC,BT>(vr, vi, lane, w, p.x, p.y); }
    #define CRXW(WM,ACT) { float2 p = scs[idx]; idx++; \
        applycrxW<WM>(vr, vi, t7, ex, p.x, p.y, (ACT)); }

    // wire -> storage bit: 0:7 1:2 2:6 3:1 4:5 5:0 6:4 7:W8 8:3 9:W9
    #pragma unroll 1
    for (int layer = 0; layer < 2; ++layer) {
        FUSED(7) FUSED(2) FUSED(6) FUSED(1) FUSED(5)
        FUSED(0) FUSED(4) FUSEDW(1) FUSED(3) FUSEDW(2)
        // forward ring
        CRX(7,2) CRX(2,6) CRX(6,1) CRX(1,5) CRX(5,0) CRX(0,4)
        CRXW(1, (lane & 2) != 0)
        CRX(8,3)
        CRXW(2, (lane & 1) != 0)
        CRX(9,7)
        // backward ring
        CRX(9,3)
        CRXW(1, (lane & 1) != 0)
        CRX(8,4) CRX(4,0) CRX(0,5) CRX(5,1) CRX(1,6) CRX(6,2) CRX(2,7)
        CRXW(2, (lane & 16) != 0)
    }

    // ---- measurements: per-thread partials P[30], single block reduction ----
    float P[30];
    float e[8];
    #pragma unroll
    for (int m = 0; m < 8; ++m) e[m] = vr[m]*vr[m] + vi[m]*vi[m];
    const float S8 = ((e[0]+e[1]) + (e[2]+e[3])) + ((e[4]+e[5]) + (e[6]+e[7]));

    // Z partials (wire -> bit)
    P[25] = ((e[0]-e[1]) + (e[2]-e[3])) + ((e[4]-e[5]) + (e[6]-e[7]));   // wire5, B0
    P[23] = ((e[0]+e[1]) - (e[2]+e[3])) + ((e[4]+e[5]) - (e[6]+e[7]));   // wire3, B1
    P[21] = ((e[0]+e[1]) + (e[2]+e[3])) - ((e[4]+e[5]) + (e[6]+e[7]));   // wire1, B2
    P[28] = (lane & 1)  ? -S8 : S8;   // wire8, B3
    P[26] = (lane & 2)  ? -S8 : S8;   // wire6, B4
    P[24] = (lane & 4)  ? -S8 : S8;   // wire4, B5
    P[22] = (lane & 8)  ? -S8 : S8;   // wire2, B6
    P[20] = (lane & 16) ? -S8 : S8;   // wire0, B7
    P[27] = (w & 1)     ? -S8 : S8;   // wire7, B8
    P[29] = (w & 2)     ? -S8 : S8;   // wire9, B9

    // X,Y reg-bit wires (explicit x2 scaling)
    #define XYREG(v, a0,b0, a1,b1, a2,b2, a3,b3) { \
        float xr = (vr[a0]*vr[b0] + vi[a0]*vi[b0]) + (vr[a1]*vr[b1] + vi[a1]*vi[b1]) \
                 + (vr[a2]*vr[b2] + vi[a2]*vi[b2]) + (vr[a3]*vr[b3] + vi[a3]*vi[b3]); \
        float xi = (vr[a0]*vi[b0] - vi[a0]*vr[b0]) + (vr[a1]*vi[b1] - vi[a1]*vr[b1]) \
                 + (vr[a2]*vi[b2] - vi[a2]*vr[b2]) + (vr[a3]*vi[b3] - vi[a3]*vr[b3]); \
        P[v] = 2.0f * xr; P[10 + (v)] = 2.0f * xi; }
    XYREG(5, 0,1, 2,3, 4,5, 6,7)    // B0
    XYREG(3, 0,2, 1,3, 4,6, 5,7)    // B1
    XYREG(1, 0,4, 1,5, 2,6, 3,7)    // B2
    #undef XYREG

    // X,Y lane-bit wires (pair double-counting provides the x2)
    #define XYLANE(v, LM) { \
        const float sgn = (lane & (LM)) ? -1.f : 1.f; \
        float zr = 0.f, zi = 0.f; \
        _Pragma("unroll") \
        for (int m = 0; m < 8; ++m) { \
            float pr = __shfl_xor_sync(0xffffffffu, vr[m], (LM)); \
            float pi = __shfl_xor_sync(0xffffffffu, vi[m], (LM)); \
            zr += vr[m]*pr + vi[m]*pi; \
            zi += vr[m]*pi - vi[m]*pr; \
        } \
        P[v] = zr; P[10 + (v)] = sgn * zi; }
    XYLANE(8, 1)    // B3
    XYLANE(6, 2)    // B4
    XYLANE(4, 4)    // B5
    XYLANE(2, 8)    // B6
    XYLANE(0, 16)   // B7
    #undef XYLANE

    // X,Y warp-bit wires: one exchange serves both
    __syncthreads();
    #pragma unroll
    for (int m = 0; m < 8; ++m) ex[m][t7] = make_float2(vr[m], vi[m]);
    __syncthreads();
    {
        const int p8 = t7 ^ 32;
        const float sgn8 = (w & 1) ? -1.f : 1.f;
        float zr = 0.f, zi = 0.f;
        #pragma unroll
        for (int m = 0; m < 8; ++m) {
            float2 pv = ex[m][p8];
            zr += vr[m]*pv.x + vi[m]*pv.y;
            zi += vr[m]*pv.y - vi[m]*pv.x;
        }
        P[7] = zr; P[17] = sgn8 * zi;
    }
    {
        const int p9 = t7 ^ 64;
        const float sgn9 = (w & 2) ? -1.f : 1.f;
        float zr = 0.f, zi = 0.f;
        #pragma unroll
        for (int m = 0; m < 8; ++m) {
            float2 pv = ex[m][p9];
            zr += vr[m]*pv.x + vi[m]*pv.y;
            zi += vr[m]*pv.y - vi[m]*pv.x;
        }
        P[9] = zr; P[19] = sgn9 * zi;
    }

    // dump partials + 2-level block reduction
    #pragma unroll
    for (int k = 0; k < 30; ++k) ptbuf[t7 * 33 + k] = P[k];
    __syncthreads();
    if (lane < 30) {    // each warp reduces its own 32 rows
        float s0 = 0.f, s1 = 0.f;
        #pragma unroll
        for (int t = 0; t < 32; t += 2) {
            s0 += ptbuf[(w * 32 + t)     * 33 + lane];
            s1 += ptbuf[(w * 32 + t + 1) * 33 + lane];
        }
        wpart[w][lane] = s0 + s1;
    }
    __syncthreads();

    // publish per-branch expvals; last block for this bt does the combine
    if (t7 < NOUT) {
        float s = (wpart[0][t7] + wpart[1][t7]) + (wpart[2][t7] + wpart[3][t7]);
        g_m[br][bt][t7] = s;
        __threadfence();
    }
    __syncthreads();
    if (t7 == 0) {
        unsigned int old = atomicAdd(&g_cnt[bt], 1u);
        sIsLast = (old == 2u);
    }
    __syncthreads();
    if (sIsLast) {
        if (t7 < NOUT) {
            __threadfence();
            float m1 = g_m[0][bt][t7];
            float m2 = g_m[1][bt][t7];
            float m3 = g_m[2][bt][t7];
            float ar = ar_[0], ai = ai_[0];
            float brv = br_[0], bi = bi_[0];
            float gr = gr_[0], gi = gi_[0];
            float norm = sqrtf(ar*ar + ai*ai + brv*brv + bi*bi + gr*gr + gi*gi + 1e-9f);
            float re = (ar * m1 + brv * m2 + gr * m3) / norm;
            float im = (ai * m1 + bi * m2 + gi * m3) / norm;
            out[bt * NOUT + t7] = sqrtf(re * re + im * im);
        }
        if (t7 == 0) g_cnt[bt] = 0u;   // reset for next graph replay
    }
}

extern "C" void kernel_launch(void* const* d_in, const int* in_sizes, int n_in,
                              void* d_out, int out_size)
{
    // d_in order: x, W1, b1, W2, b2, W3, b3, base1, base2, base3, ar, ai, br, bi, gr, gi
    qsb_params<<<2 * 75, 256>>>(
        (const float*)d_in[0],
        (const float*)d_in[1], (const float*)d_in[2], (const float*)d_in[7],
        (const float*)d_in[3], (const float*)d_in[4], (const float*)d_in[8],
        (const float*)d_in[5], (const float*)d_in[6], (const float*)d_in[9]);

    qsb_circuit<<<3 * BATCH, 128>>>(
        (const float*)d_in[10], (const float*)d_in[11],
        (const float*)d_in[12], (const float*)d_in[13],
        (const float*)d_in[14], (const float*)d_in[15],
        (float*)d_out);
}